// round 8
// baseline (speedup 1.0000x reference)
#include <cuda_runtime.h>

// Fixed problem shape: B=512, Np=128, Ng=128, TIME=5
#define BATCH 512
#define NP 128
#define NG 128
#define TSTEPS 5
#define GI (NG * TSTEPS)          // 640 interpolated gt points
#define NSLICE 4
#define SLICE_PTS (GI / NSLICE)   // 160 points per slice
#define NJ (SLICE_PTS / 4)        // 40 groups of 4 points
#define PPT 2                     // pred points per thread
#define CTA_THREADS 256           // 64 pred-pairs x 4 slices

__device__ float        g_partial[BATCH];
__device__ unsigned int g_count = 0;

// ---------- packed f32x2 helpers (sm_103a) ----------
__device__ __forceinline__ unsigned long long pk2(float lo, float hi) {
    unsigned long long r;
    asm("mov.b64 %0, {%1, %2};" : "=l"(r) : "f"(lo), "f"(hi));
    return r;
}
__device__ __forceinline__ unsigned long long add2(unsigned long long a, unsigned long long b) {
    unsigned long long r;
    asm("add.rn.f32x2 %0, %1, %2;" : "=l"(r) : "l"(a), "l"(b));
    return r;
}
__device__ __forceinline__ unsigned long long mul2(unsigned long long a, unsigned long long b) {
    unsigned long long r;
    asm("mul.rn.f32x2 %0, %1, %2;" : "=l"(r) : "l"(a), "l"(b));
    return r;
}
__device__ __forceinline__ unsigned long long fma2(unsigned long long a, unsigned long long b,
                                                   unsigned long long c) {
    unsigned long long r;
    asm("fma.rn.f32x2 %0, %1, %2, %3;" : "=l"(r) : "l"(a), "l"(b), "l"(c));
    return r;
}

__device__ __forceinline__ float smooth_l1_elem(float d) {
    d = fabsf(d);
    return (d < 1.0f) ? (0.5f * d * d) : (d - 0.5f);
}

// One CTA per batch, 256 threads. Thread (sl = tid>>6, q = tid&63) scans
// gt-interp slice [160*sl, 160*sl+160) for pred points 2q and 2q+1.
// Each LDS.128 pair now serves TWO pred points (halves smem-crossbar traffic,
// which is the measured structural bottleneck).
__global__ void __launch_bounds__(CTA_THREADS, 4)
dm_fused(const float2* __restrict__ pred,
         const float2* __restrict__ gt,
         float* __restrict__ out) {
    __shared__ __align__(16) float nxs[GI];   // negated interp x (SoA)
    __shared__ __align__(16) float nys[GI];   // negated interp y
    __shared__ unsigned int s_amin[NSLICE][NP];
    __shared__ float s_warp[8];
    __shared__ float red[CTA_THREADS];
    __shared__ int   s_is_last;

    const int b    = blockIdx.x;
    const int tid  = threadIdx.x;
    const int q    = tid & 63;      // pred pair id
    const int sl   = tid >> 6;      // slice id 0..3
    const int lane = tid & 31;
    const int wid  = tid >> 5;
    const float2* gtb = gt + b * NG;

    // Build negated interpolation table: interp[n*5+t] = gt[n]*s + gt[n-1]*(1-s)
    for (int i = tid; i < GI; i += CTA_THREADS) {
        int n = i / TSTEPS;
        int t = i - n * TSTEPS;
        float s = (float)t / (float)TSTEPS;
        float2 c  = __ldg(&gtb[n]);
        float2 pv = __ldg(&gtb[(n + NG - 1) & (NG - 1)]);
        nxs[i] = -(c.x * s + pv.x * (1.0f - s));
        nys[i] = -(c.y * s + pv.y * (1.0f - s));
    }
    __syncthreads();

    const float2 pA = pred[b * NP + 2 * q + 0];
    const float2 pB = pred[b * NP + 2 * q + 1];
    const unsigned long long pxA = pk2(pA.x, pA.x), pyA = pk2(pA.y, pA.y);
    const unsigned long long pxB = pk2(pB.x, pB.x), pyB = pk2(pB.y, pB.y);

    // In-loop key: (dist_bits & 0xFFFFFF80) | j  (j = 0..39, fits 7 bits).
    // dist >= 0 -> fp bits uint-monotonic; min == first-occurrence argmin.
    unsigned int A0 = 0xFFFFFFFFu, A1 = 0xFFFFFFFFu, A2 = 0xFFFFFFFFu, A3 = 0xFFFFFFFFu;
    unsigned int B0 = 0xFFFFFFFFu, B1 = 0xFFFFFFFFu, B2 = 0xFFFFFFFFu, B3 = 0xFFFFFFFFu;

    const int base0 = sl * SLICE_PTS;
    const ulonglong2* xs2 = reinterpret_cast<const ulonglong2*>(&nxs[base0]);
    const ulonglong2* ys2 = reinterpret_cast<const ulonglong2*>(&nys[base0]);

    #pragma unroll 8
    for (unsigned int j = 0; j < NJ; ++j) {
        ulonglong2 xv = xs2[j];   // LDS.128: two f32x2 pairs of -interp.x
        ulonglong2 yv = ys2[j];   // serves BOTH pred points
        // pred A
        {
            unsigned long long dxa = add2(pxA, xv.x);
            unsigned long long dxb = add2(pxA, xv.y);
            unsigned long long dya = add2(pyA, yv.x);
            unsigned long long dyb = add2(pyA, yv.y);
            unsigned long long da  = fma2(dya, dya, mul2(dxa, dxa));
            unsigned long long db  = fma2(dyb, dyb, mul2(dxb, dxb));
            A0 = min(A0, (((unsigned int)da)         & 0xFFFFFF80u) | j);
            A1 = min(A1, (((unsigned int)(da >> 32)) & 0xFFFFFF80u) | j);
            A2 = min(A2, (((unsigned int)db)         & 0xFFFFFF80u) | j);
            A3 = min(A3, (((unsigned int)(db >> 32)) & 0xFFFFFF80u) | j);
        }
        // pred B
        {
            unsigned long long dxa = add2(pxB, xv.x);
            unsigned long long dxb = add2(pxB, xv.y);
            unsigned long long dya = add2(pyB, yv.x);
            unsigned long long dyb = add2(pyB, yv.y);
            unsigned long long da  = fma2(dya, dya, mul2(dxa, dxa));
            unsigned long long db  = fma2(dyb, dyb, mul2(dxb, dxb));
            B0 = min(B0, (((unsigned int)da)         & 0xFFFFFF80u) | j);
            B1 = min(B1, (((unsigned int)(da >> 32)) & 0xFFFFFF80u) | j);
            B2 = min(B2, (((unsigned int)db)         & 0xFFFFFF80u) | j);
            B3 = min(B3, (((unsigned int)(db >> 32)) & 0xFFFFFF80u) | j);
        }
    }
    // Rebuild local keys: dist -> bits [8..31], local idx (j*4+k) in [0..159].
    {
        unsigned int f0 = (A0 & 0xFFFFFF00u) | (((A0 & 0x7Fu) << 2) | 0u);
        unsigned int f1 = (A1 & 0xFFFFFF00u) | (((A1 & 0x7Fu) << 2) | 1u);
        unsigned int f2 = (A2 & 0xFFFFFF00u) | (((A2 & 0x7Fu) << 2) | 2u);
        unsigned int f3 = (A3 & 0xFFFFFF00u) | (((A3 & 0x7Fu) << 2) | 3u);
        unsigned int best4 = min(min(f0, f1), min(f2, f3));
        // Global key: dist bits [10..31], global interp idx in bits [0..9].
        s_amin[sl][2 * q + 0] = (best4 & 0xFFFFFC00u)
                              | (unsigned int)(base0 + (best4 & 0xFFu));
    }
    {
        unsigned int f0 = (B0 & 0xFFFFFF00u) | (((B0 & 0x7Fu) << 2) | 0u);
        unsigned int f1 = (B1 & 0xFFFFFF00u) | (((B1 & 0x7Fu) << 2) | 1u);
        unsigned int f2 = (B2 & 0xFFFFFF00u) | (((B2 & 0x7Fu) << 2) | 2u);
        unsigned int f3 = (B3 & 0xFFFFFF00u) | (((B3 & 0x7Fu) << 2) | 3u);
        unsigned int best4 = min(min(f0, f1), min(f2, f3));
        s_amin[sl][2 * q + 1] = (best4 & 0xFFFFFC00u)
                              | (unsigned int)(base0 + (best4 & 0xFFu));
    }
    __syncthreads();

    float wsum = 0.0f;
    if (tid < NP) {
        unsigned int best = min(min(s_amin[0][tid], s_amin[1][tid]),
                                min(s_amin[2][tid], s_amin[3][tid]));
        int bi = (int)(best & 0x3FFu);
        float2 pp = __ldg(&pred[b * NP + tid]);
        float mx = -nxs[bi];
        float my = -nys[bi];
        float l = smooth_l1_elem(pp.x - mx) + smooth_l1_elem(pp.y - my);
        #pragma unroll
        for (int o = 16; o > 0; o >>= 1)
            l += __shfl_xor_sync(0xFFFFFFFFu, l, o);
        wsum = l;
    }
    if (tid < NP && lane == 0) s_warp[wid] = wsum;
    __syncthreads();

    if (tid == 0) {
        g_partial[b] = (s_warp[0] + s_warp[1]) + (s_warp[2] + s_warp[3]);
        __threadfence();
        unsigned int old = atomicAdd(&g_count, 1u);
        s_is_last = (old == (unsigned int)(gridDim.x - 1));
    }
    __syncthreads();

    if (s_is_last) {
        __threadfence();
        // Deterministic: fixed per-thread loads, fixed tree.
        red[tid] = __ldcg(&g_partial[tid]) + __ldcg(&g_partial[tid + 256]);
        __syncthreads();
        #pragma unroll
        for (int k = 128; k > 0; k >>= 1) {
            if (tid < k) red[tid] += red[tid + k];
            __syncthreads();
        }
        if (tid == 0) {
            out[0] = red[0] * (1.0f / (float)(BATCH * NP * 2));
            g_count = 0;   // reset for next graph replay
        }
    }
}

extern "C" void kernel_launch(void* const* d_in, const int* in_sizes, int n_in,
                              void* d_out, int out_size) {
    const float2* pred = (const float2*)d_in[1];
    const float2* gt   = (const float2*)d_in[2];
    dm_fused<<<BATCH, CTA_THREADS>>>(pred, gt, (float*)d_out);
}

// round 9
// speedup vs baseline: 1.5038x; 1.5038x over previous
#include <cuda_runtime.h>

// Fixed problem shape: B=512, Np=128, Ng=128, TIME=5
#define BATCH 512
#define NP 128
#define NG 128
#define TSTEPS 5
#define GI (NG * TSTEPS)          // 640 interpolated gt points
#define NSEG 128                  // segments (one per gt vertex)
#define NSLICE 4                  // segment slices per pred
#define SEGS_PER_SLICE (NSEG / NSLICE)     // 32
#define PAIRS_PER_SLICE (SEGS_PER_SLICE/2) // 16
#define PREDS_PER_CTA 64
#define CTA_THREADS 256           // 64 preds x 4 slices
#define NCTA (BATCH * (NP / PREDS_PER_CTA))  // 1024

__device__ float        g_partial[NCTA];
__device__ unsigned int g_count = 0;

// ---------- packed f32x2 helpers (sm_103a) ----------
__device__ __forceinline__ unsigned long long pk2(float lo, float hi) {
    unsigned long long r;
    asm("mov.b64 %0, {%1, %2};" : "=l"(r) : "f"(lo), "f"(hi));
    return r;
}
__device__ __forceinline__ unsigned long long add2(unsigned long long a, unsigned long long b) {
    unsigned long long r;
    asm("add.rn.f32x2 %0, %1, %2;" : "=l"(r) : "l"(a), "l"(b));
    return r;
}
__device__ __forceinline__ unsigned long long mul2(unsigned long long a, unsigned long long b) {
    unsigned long long r;
    asm("mul.rn.f32x2 %0, %1, %2;" : "=l"(r) : "l"(a), "l"(b));
    return r;
}
__device__ __forceinline__ unsigned long long fma2(unsigned long long a, unsigned long long b,
                                                   unsigned long long c) {
    unsigned long long r;
    asm("fma.rn.f32x2 %0, %1, %2, %3;" : "=l"(r) : "l"(a), "l"(b), "l"(c));
    return r;
}
__device__ __forceinline__ float lo2(unsigned long long v) {
    return __uint_as_float((unsigned int)v);
}
__device__ __forceinline__ float hi2(unsigned long long v) {
    return __uint_as_float((unsigned int)(v >> 32));
}

__device__ __forceinline__ float smooth_l1_elem(float d) {
    d = fabsf(d);
    return (d < 1.0f) ? (0.5f * d * d) : (d - 0.5f);
}

#define RMAGIC 12582912.0f   // 1.5 * 2^23: (u+RMAGIC)-RMAGIC = round-to-nearest int

// Two CTAs per batch (64 preds each). Thread (sl = tid>>6, q = tid&63) scans
// segment slice [32*sl, 32*sl+32) analytically (closed-form quadratic min over
// the 5 samples of each segment) for pred point q. 5x fewer candidate evals.
__global__ void __launch_bounds__(CTA_THREADS, 7)
dm_fused(const float2* __restrict__ pred,
         const float2* __restrict__ gt,
         float* __restrict__ out) {
    // Exact-reference interpolation table (for the final matched-point gather).
    __shared__ __align__(16) float2 interp[GI];              // 5120 B
    // Per-segment analytic data, packed for f32x2 pair processing:
    // A4[p] = {-ax[2p], -ax[2p+1], -ay[2p], -ay[2p+1]}
    // D4[p] = {-2dx[2p], -2dx[2p+1], -2dy[2p], -2dy[2p+1]}
    // Q4[p] = {qq[2p],   qq[2p+1],   d2[2p],   d2[2p+1]}   qq = -2.5/d2
    __shared__ __align__(16) float A4[NSEG / 2 * 4];
    __shared__ __align__(16) float D4[NSEG / 2 * 4];
    __shared__ __align__(16) float Q4[NSEG / 2 * 4];
    __shared__ unsigned int s_amin[NSLICE][PREDS_PER_CTA];
    __shared__ float s_warp[2];
    __shared__ float red[CTA_THREADS];
    __shared__ int   s_is_last;

    const int cta  = blockIdx.x;
    const int b    = cta >> 1;
    const int half = cta & 1;
    const int tid  = threadIdx.x;
    const int q    = tid & 63;      // pred id within CTA
    const int sl   = tid >> 6;      // slice id 0..3
    const float2* gtb = gt + b * NG;

    // Build exact interp table: interp[n*5+t] = gt[n]*s + gt[n-1]*(1-s), s=t/5
    for (int i = tid; i < GI; i += CTA_THREADS) {
        int n = i / TSTEPS;
        int t = i - n * TSTEPS;
        float s = (float)t / (float)TSTEPS;
        float2 c  = __ldg(&gtb[n]);
        float2 pv = __ldg(&gtb[(n + NG - 1) & (NG - 1)]);
        float2 v;
        v.x = c.x * s + pv.x * (1.0f - s);
        v.y = c.y * s + pv.y * (1.0f - s);
        interp[i] = v;
    }
    // Build per-segment analytic data (one thread per segment)
    if (tid < NSEG) {
        int n = tid;
        float2 a = __ldg(&gtb[(n + NG - 1) & (NG - 1)]);
        float2 c = __ldg(&gtb[n]);
        float dx = c.x - a.x, dy = c.y - a.y;
        float d2 = dx * dx + dy * dy;
        float qq = -2.5f / d2;
        int pr = n >> 1, pa = n & 1;
        A4[4 * pr + pa]     = -a.x;
        A4[4 * pr + 2 + pa] = -a.y;
        D4[4 * pr + pa]     = -2.0f * dx;
        D4[4 * pr + 2 + pa] = -2.0f * dy;
        Q4[4 * pr + pa]     = qq;
        Q4[4 * pr + 2 + pa] = d2;
    }
    __syncthreads();

    const float2 pp = pred[b * NP + half * PREDS_PER_CTA + q];
    const unsigned long long px2 = pk2(pp.x, pp.x);
    const unsigned long long py2 = pk2(pp.y, pp.y);
    const unsigned long long MAG2  = pk2(RMAGIC, RMAGIC);
    const unsigned long long NMAG2 = pk2(-RMAGIC, -RMAGIC);

    // Per-pair (even/odd segment) argmin accumulators.
    // Key: (analytic_min_dist_bits & 0xFFFFFF80) | j  (j = pair index, 0..15).
    unsigned int accE = 0xFFFFFFFFu, accO = 0xFFFFFFFFu;

    const int pair0 = sl * PAIRS_PER_SLICE;
    const ulonglong2* A2v = reinterpret_cast<const ulonglong2*>(A4) + pair0;
    const ulonglong2* D2v = reinterpret_cast<const ulonglong2*>(D4) + pair0;
    const ulonglong2* Q2v = reinterpret_cast<const ulonglong2*>(Q4) + pair0;

    #pragma unroll 8
    for (unsigned int j = 0; j < PAIRS_PER_SLICE; ++j) {
        ulonglong2 av = A2v[j];  // (-ax pair, -ay pair)
        ulonglong2 dv = D2v[j];  // (-2dx pair, -2dy pair)
        ulonglong2 qv = Q2v[j];  // (qq pair, d2 pair)
        unsigned long long ex2 = add2(px2, av.x);          // e = p - a
        unsigned long long ey2 = add2(py2, av.y);
        unsigned long long dm2 = fma2(ey2, dv.y, mul2(ex2, dv.x)); // -2 e.d
        unsigned long long e22 = fma2(ey2, ey2, mul2(ex2, ex2));   // |e|^2
        unsigned long long u2  = mul2(dm2, qv.x);          // 5 e.d / d2
        unsigned long long r2  = add2(add2(u2, MAG2), NMAG2);   // round(u)
        // scalar tails (clamp + D eval + key), even then odd
        {
            float kf = fminf(fmaxf(lo2(r2), 0.0f), 4.0f);
            float tk = kf * 0.2f;
            float D  = fmaf(tk, fmaf(tk, lo2(qv.y), lo2(dm2)), lo2(e22));
            accE = min(accE, (__float_as_uint(D) & 0xFFFFFF80u) | j);
        }
        {
            float kf = fminf(fmaxf(hi2(r2), 0.0f), 4.0f);
            float tk = kf * 0.2f;
            float D  = fmaf(tk, fmaf(tk, hi2(qv.y), hi2(dm2)), hi2(e22));
            accO = min(accO, (__float_as_uint(D) & 0xFFFFFF80u) | j);
        }
    }
    // Rebuild keys with global segment index n (7 bits) in the low field.
    const unsigned int base0 = (unsigned int)(sl * SEGS_PER_SLICE);
    unsigned int keyE = (accE & 0xFFFFFF80u) | (base0 + ((accE & 0x7Fu) << 1));
    unsigned int keyO = (accO & 0xFFFFFF80u) | (base0 + ((accO & 0x7Fu) << 1) + 1u);
    s_amin[sl][q] = min(keyE, keyO);
    __syncthreads();

    float wsum = 0.0f;
    if (tid < PREDS_PER_CTA) {   // q == tid, pp is this pred point
        unsigned int best = min(min(s_amin[0][tid], s_amin[1][tid]),
                                min(s_amin[2][tid], s_amin[3][tid]));
        int n  = (int)(best & 0x7Fu);
        int pr = n >> 1, pa = n & 1;
        // recompute k for the winning segment
        float ex = pp.x + A4[4 * pr + pa];
        float ey = pp.y + A4[4 * pr + 2 + pa];
        float dm = fmaf(ey, D4[4 * pr + 2 + pa], ex * D4[4 * pr + pa]);
        float u  = dm * Q4[4 * pr + pa];
        float kf = fminf(fmaxf((u + RMAGIC) - RMAGIC, 0.0f), 4.0f);
        int idx  = n * TSTEPS + (int)kf;
        float2 m = interp[idx];                 // exact reference value
        float l = smooth_l1_elem(pp.x - m.x) + smooth_l1_elem(pp.y - m.y);
        #pragma unroll
        for (int o = 16; o > 0; o >>= 1)
            l += __shfl_xor_sync(0xFFFFFFFFu, l, o);
        if ((tid & 31) == 0) s_warp[tid >> 5] = l;
    }
    __syncthreads();

    if (tid == 0) {
        g_partial[cta] = s_warp[0] + s_warp[1];
        __threadfence();
        unsigned int old = atomicAdd(&g_count, 1u);
        s_is_last = (old == (unsigned int)(gridDim.x - 1));
    }
    __syncthreads();

    if (s_is_last) {
        __threadfence();
        // Deterministic final reduction: fixed per-thread loads, fixed tree.
        red[tid] = __ldcg(&g_partial[tid])
                 + __ldcg(&g_partial[tid + 256])
                 + __ldcg(&g_partial[tid + 512])
                 + __ldcg(&g_partial[tid + 768]);
        __syncthreads();
        #pragma unroll
        for (int k = 128; k > 0; k >>= 1) {
            if (tid < k) red[tid] += red[tid + k];
            __syncthreads();
        }
        if (tid == 0) {
            out[0] = red[0] * (1.0f / (float)(BATCH * NP * 2));
            g_count = 0;   // reset for next graph replay
        }
    }
}

extern "C" void kernel_launch(void* const* d_in, const int* in_sizes, int n_in,
                              void* d_out, int out_size) {
    const float2* pred = (const float2*)d_in[1];
    const float2* gt   = (const float2*)d_in[2];
    dm_fused<<<NCTA, CTA_THREADS>>>(pred, gt, (float*)d_out);
}